// round 15
// baseline (speedup 1.0000x reference)
#include <cuda_runtime.h>
#include <cuda_fp16.h>
#include <mma.h>
#include <math.h>

using namespace nvcuda;

#define BATCH   4
#define SEQ     1024
#define DMODEL  256
#define NHEAD   8
#define DHEAD   32
#define DFF     1024
#define NLAYER  6
#define TOK     (BATCH*SEQ)
#define TD      (TOK*DMODEL)          // 1,048,576

__device__ __align__(16) float  g_fscratch[2*TD];
// Xh,ENC,Q,K,V,C (6TD) + H (4TD) + weights (6TD) + crossK (6TD) + crossV (6TD)
__device__ __align__(16) __half g_hscratch[16*1024*1024 + 12*TD];
__device__ int g_maskflags[64];

#define OFF_X 0
#define OFF_T TD

#define HOFF_XH  0
#define HOFF_ENC (1*TD)
#define HOFF_Q   (2*TD)
#define HOFF_K   (3*TD)
#define HOFF_V   (4*TD)
#define HOFF_C   (5*TD)
#define HOFF_H   (6*TD)
#define HOFF_W   (10*TD)
#define HOFF_KC  (16*1024*1024)
#define HOFF_VC  (HOFF_KC + 6*TD)
#define WSEG     393216               // NL*256*256

// ---------------- cp.async helpers ----------------
__device__ __forceinline__ void cpa16(void* dst, const void* src) {
    unsigned s = (unsigned)__cvta_generic_to_shared(dst);
    asm volatile("cp.async.cg.shared.global [%0], [%1], 16;\n" :: "r"(s), "l"(src));
}
__device__ __forceinline__ void cpa_commit() {
    asm volatile("cp.async.commit_group;\n");
}
template<int N>
__device__ __forceinline__ void cpa_wait() {
    asm volatile("cp.async.wait_group %0;\n" :: "n"(N));
}

// ---------------- raw mma helpers ----------------
__device__ __forceinline__ void mma16816(float* c, const unsigned* a, const unsigned* b) {
    asm volatile("mma.sync.aligned.m16n8k16.row.col.f32.f16.f16.f32 "
        "{%0,%1,%2,%3}, {%4,%5,%6,%7}, {%8,%9}, {%0,%1,%2,%3};"
        : "+f"(c[0]), "+f"(c[1]), "+f"(c[2]), "+f"(c[3])
        : "r"(a[0]), "r"(a[1]), "r"(a[2]), "r"(a[3]), "r"(b[0]), "r"(b[1]));
}
__device__ __forceinline__ void ldsm4(unsigned* r, unsigned addr) {
    asm volatile("ldmatrix.sync.aligned.m8n8.x4.shared.b16 {%0,%1,%2,%3}, [%4];"
        : "=r"(r[0]), "=r"(r[1]), "=r"(r[2]), "=r"(r[3]) : "r"(addr));
}
__device__ __forceinline__ void ldsm4t(unsigned* r, unsigned addr) {
    asm volatile("ldmatrix.sync.aligned.m8n8.x4.trans.shared.b16 {%0,%1,%2,%3}, [%4];"
        : "=r"(r[0]), "=r"(r[1]), "=r"(r[2]), "=r"(r[3]) : "r"(addr));
}
__device__ __forceinline__ float ex2(float x) {
    float y; asm("ex2.approx.f32 %0, %1;" : "=f"(y) : "f"(x)); return y;
}

// ---------------- mask tile flags ----------------
__global__ void maskflag_kernel(const int* __restrict__ dec_mask,
                                const int* __restrict__ enc_mask) {
    int id = blockIdx.x;
    const int* m = (id < 32) ? dec_mask : enc_mask;
    int loc = id & 31;
    int b = loc >> 3, t = loc & 7;
    int v = m[b*SEQ + t*128 + threadIdx.x];
    int any = __syncthreads_or(v != 0);
    if (threadIdx.x == 0) g_maskflags[id] = any;
}

// ---------------- batched fp32 -> fp16 convert (one launch) ----------------
struct CvtAll {
    const float* src[11];
    __half*      dst[11];
    int          size[11];
};
__global__ void cvt_all_kernel(CvtAll ca) {
    long idx = ((long)blockIdx.x*blockDim.x + threadIdx.x)*4;
    #pragma unroll
    for (int s = 0; s < 11; s++) {
        if (idx < ca.size[s]) {
            float4 v = *(const float4*)&ca.src[s][idx];
            __half2* o = (__half2*)&ca.dst[s][idx];
            o[0] = __floats2half2_rn(v.x, v.y);
            o[1] = __floats2half2_rn(v.z, v.w);
            return;
        }
        idx -= ca.size[s];
    }
}

// ---------------- positional embedding ----------------
__device__ __forceinline__ float pe_val(int l, int d) {
    int j = d & 127;
    double e = -(2.0*(double)j/256.0) * 9.210340371976184;
    float invf = (float)exp(e);
    float arg = (float)l * invf;
    return (d < 128) ? sinf(arg) : cosf(arg);
}

// ---------------- embed (+PE layer 0) ----------------
__global__ void embed_kernel(const float* __restrict__ dec,
                             const float* __restrict__ W,
                             const float* __restrict__ b,
                             float* __restrict__ x, __half* __restrict__ xh) {
    int row = blockIdx.x;
    int d   = threadIdx.x;
    const float* in = dec + row*3;
    float acc = b[d] + in[0]*W[d] + in[1]*W[DMODEL+d] + in[2]*W[2*DMODEL+d]
              + pe_val(row & (SEQ-1), d);
    x [row*DMODEL + d] = acc;
    xh[row*DMODEL + d] = __float2half(acc);
}

// ---------------- LayerNorm: warp-per-row ----------------
__global__ __launch_bounds__(256)
void ln_kernel(const float* __restrict__ t,
               const float* __restrict__ g,
               const float* __restrict__ b,
               float* __restrict__ out, __half* __restrict__ outh,
               int addpe) {
    int w    = threadIdx.x >> 5;
    int lane = threadIdx.x & 31;
    int row  = blockIdx.x*8 + w;
    int cb   = lane*8;

    const float* tr = t + (size_t)row*DMODEL + cb;
    float4 v0 = *(const float4*)tr;
    float4 v1 = *(const float4*)(tr + 4);

    float s1 = (v0.x + v0.y) + (v0.z + v0.w) + (v1.x + v1.y) + (v1.z + v1.w);
    float s2 = v0.x*v0.x + v0.y*v0.y + v0.z*v0.z + v0.w*v0.w
             + v1.x*v1.x + v1.y*v1.y + v1.z*v1.z + v1.w*v1.w;
    #pragma unroll
    for (int o = 16; o; o >>= 1) {
        s1 += __shfl_xor_sync(0xffffffffu, s1, o);
        s2 += __shfl_xor_sync(0xffffffffu, s2, o);
    }
    float mean = s1 * (1.0f/DMODEL);
    float var  = s2 * (1.0f/DMODEL) - mean*mean;
    float rstd = rsqrtf(var + 1e-5f);

    float4 g0 = *(const float4*)&g[cb];
    float4 g1 = *(const float4*)&g[cb + 4];
    float4 e0 = *(const float4*)&b[cb];
    float4 e1 = *(const float4*)&b[cb + 4];

    float o8[8];
    o8[0]=(v0.x-mean)*rstd*g0.x+e0.x; o8[1]=(v0.y-mean)*rstd*g0.y+e0.y;
    o8[2]=(v0.z-mean)*rstd*g0.z+e0.z; o8[3]=(v0.w-mean)*rstd*g0.w+e0.w;
    o8[4]=(v1.x-mean)*rstd*g1.x+e1.x; o8[5]=(v1.y-mean)*rstd*g1.y+e1.y;
    o8[6]=(v1.z-mean)*rstd*g1.z+e1.z; o8[7]=(v1.w-mean)*rstd*g1.w+e1.w;
    if (addpe) {
        int l = row & (SEQ-1);
        #pragma unroll
        for (int q = 0; q < 8; q++) o8[q] += pe_val(l, cb + q);
    }
    float* op = out + (size_t)row*DMODEL + cb;
    *(float4*)op       = make_float4(o8[0],o8[1],o8[2],o8[3]);
    *(float4*)(op + 4) = make_float4(o8[4],o8[5],o8[6],o8[7]);
    __half2* hp = (__half2*)(outh + (size_t)row*DMODEL + cb);
    hp[0] = __floats2half2_rn(o8[0], o8[1]);
    hp[1] = __floats2half2_rn(o8[2], o8[3]);
    hp[2] = __floats2half2_rn(o8[4], o8[5]);
    hp[3] = __floats2half2_rn(o8[6], o8[7]);
}

// ---------------- fp16 wmma GEMM (round-13 config): 64x128x64, 3-stage ------
// grid.z = layer (weights/bias/output strided by wstride/bstride/ostride).
struct GArgs {
    const __half* A[3];
    const __half* W[3];
    const float*  bi[3];
    void*         O[3];
};

#define AS_H 72
#define BS_H 136
#define GEMM_SMEM ((3*64*AS_H + 3*64*BS_H)*2)   // 79872 B

template<bool RELU, bool RES, bool OUTH>
__global__ __launch_bounds__(256)
void gemm_kernel(GArgs ga, const float* __restrict__ Rres,
                 int K, int N, int bnshift,
                 int wstride, int bstride, int ostride) {
    extern __shared__ __align__(16) char dsmc[];
    __half* As = (__half*)dsmc;
    __half* Bs = As + 3*64*AS_H;

    int tid = threadIdx.x;
    int w   = tid >> 5;
    int bx  = blockIdx.x;
    int sel = bx >> bnshift;
    int bn  = bx & ((1 << bnshift) - 1);
    int bm  = blockIdx.y;
    int bz  = blockIdx.z;

    const __half* Abase = ga.A[sel] + (size_t)(bm*64)*K;
    const __half* Wbase = ga.W[sel] + (size_t)bz*wstride + bn*128;
    const float*  bias  = ga.bi[sel] + (size_t)bz*bstride;

    int wm = w & 1;
    int wn = w >> 1;

    wmma::fragment<wmma::accumulator,16,16,16,float> c[2][2];
    #pragma unroll
    for (int i = 0; i < 2; i++)
        #pragma unroll
        for (int j = 0; j < 2; j++)
            wmma::fill_fragment(c[i][j], 0.0f);

    auto stage = [&](int t, int buf) {
        __half* Ab = As + buf*64*AS_H;
        __half* Bb = Bs + buf*64*BS_H;
        const __half* Ag = Abase + t*64;
        #pragma unroll
        for (int i = 0; i < 2; i++) {
            int s = tid + i*256;
            int r = s >> 3, c8 = s & 7;
            cpa16(&Ab[r*AS_H + c8*8], Ag + (size_t)r*K + c8*8);
        }
        const __half* Wg = Wbase + (size_t)(t*64)*N;
        #pragma unroll
        for (int i = 0; i < 4; i++) {
            int s = tid + i*256;
            int r = s >> 4, c8 = s & 15;
            cpa16(&Bb[r*BS_H + c8*8], Wg + (size_t)r*N + c8*8);
        }
        cpa_commit();
    };

    int T = K >> 6;
    stage(0, 0);
    if (T > 1) stage(1, 1);

    for (int t = 0; t < T; t++) {
        if (t + 1 < T) cpa_wait<1>(); else cpa_wait<0>();
        __syncthreads();
        if (t + 2 < T) stage(t+2, (t+2)%3);

        int buf = t % 3;
        __half* Ab = As + buf*64*AS_H;
        __half* Bb = Bs + buf*64*BS_H;
        #pragma unroll
        for (int kk = 0; kk < 4; kk++) {
            wmma::fragment<wmma::matrix_a,16,16,16,__half,wmma::row_major> a[2];
            #pragma unroll
            for (int i = 0; i < 2; i++)
                wmma::load_matrix_sync(a[i], &Ab[(wm*32 + i*16)*AS_H + kk*16], AS_H);
            #pragma unroll
            for (int j = 0; j < 2; j++) {
                wmma::fragment<wmma::matrix_b,16,16,16,__half,wmma::row_major> bf;
                wmma::load_matrix_sync(bf, &Bb[(kk*16)*BS_H + wn*32 + j*16], BS_H);
                #pragma unroll
                for (int i = 0; i < 2; i++)
                    wmma::mma_sync(c[i][j], a[i], bf, c[i][j]);
            }
        }
    }
    __syncthreads();

    float* Cs = (float*)dsmc;
    #pragma unroll
    for (int i = 0; i < 2; i++)
        #pragma unroll
        for (int j = 0; j < 2; j++)
            wmma::store_matrix_sync(&Cs[(wm*32 + i*16)*136 + wn*32 + j*16],
                                    c[i][j], 136, wmma::mem_row_major);
    __syncthreads();

    #pragma unroll
    for (int i = 0; i < 8; i++) {
        int s = tid + i*256;
        int r = s >> 5, c4 = s & 31;
        int gr = bm*64 + r;
        int gc = bn*128 + c4*4;
        float4 v  = *(float4*)&Cs[r*136 + c4*4];
        float4 bb = *(const float4*)&bias[gc];
        v.x += bb.x; v.y += bb.y; v.z += bb.z; v.w += bb.w;
        if (RES) {
            float4 rr = *(const float4*)&Rres[(size_t)gr*N + gc];
            v.x += rr.x; v.y += rr.y; v.z += rr.z; v.w += rr.w;
        }
        if (RELU) {
            v.x = fmaxf(v.x, 0.f); v.y = fmaxf(v.y, 0.f);
            v.z = fmaxf(v.z, 0.f); v.w = fmaxf(v.w, 0.f);
        }
        if (OUTH) {
            __half2* op = (__half2*)((__half*)ga.O[sel] + (size_t)bz*ostride
                                     + (size_t)gr*N + gc);
            op[0] = __floats2half2_rn(v.x, v.y);
            op[1] = __floats2half2_rn(v.z, v.w);
        } else {
            *(float4*)((float*)ga.O[sel] + (size_t)bz*ostride + (size_t)gr*N + gc) = v;
        }
    }
}

// ---------------- fused attention v5 (unchanged, passing) ----------------
#define ATTN_SMEM 47104

__global__ __launch_bounds__(256)
void attn_kernel(const __half* __restrict__ Qg, const __half* __restrict__ Kg,
                 const __half* __restrict__ Vg, __half* __restrict__ Og,
                 const int* __restrict__ mask, const int* __restrict__ flags,
                 int Lk, int causal) {
    extern __shared__ __align__(16) char smc[];
    __half* Qs     = (__half*)smc;
    __half* KsB[2] = {(__half*)(smc + 5120),  (__half*)(smc + 15360)};
    __half* VsB[2] = {(__half*)(smc + 25600), (__half*)(smc + 35840)};
    int*    smask  = (int*)(smc + 46080);

    int tid = threadIdx.x, w = tid >> 5, lane = tid & 31;
    int qt = blockIdx.x, h = blockIdx.y, b = blockIdx.z;
    int q0 = qt*64;
    int mi = w & 3, kh = w >> 2;
    int r  = lane >> 2, g = lane & 3;

    const __half* Qp = Qg + ((size_t)(b*SEQ + q0))*DMODEL + h*DHEAD;
    {
        int rr = tid >> 2, c8 = tid & 3;
        *(float4*)&Qs[rr*40 + c8*8] = *(const float4*)&Qp[(size_t)rr*DMODEL + c8*8];
    }

    auto stage_kv = [&](int it, int buf) {
        int k0 = it*128;
        const __half* Kp = Kg + ((size_t)(b*Lk + k0))*DMODEL + h*DHEAD;
        const __half* Vp = Vg + ((size_t)(b*Lk + k0))*DMODEL + h*DHEAD;
        #pragma unroll
        for (int i = 0; i < 2; i++) {
            int s = tid + i*256;
            int rr = s >> 2, c8 = s & 3;
            cpa16(&KsB[buf][rr*40 + c8*8], Kp + (size_t)rr*DMODEL + c8*8);
            cpa16(&VsB[buf][rr*40 + c8*8], Vp + (size_t)rr*DMODEL + c8*8);
        }
        if (tid < 128) smask[buf*128 + tid] = mask[b*Lk + k0 + tid];
        cpa_commit();
    };

    stage_kv(0, 0);
    __syncthreads();

    unsigned qa[2][4];
    #pragma unroll
    for (int kk = 0; kk < 2; kk++) {
        const __half* base = &Qs[(mi*16 + r)*40 + kk*16 + g*2];
        qa[kk][0] = *(const unsigned*)(base);
        qa[kk][1] = *(const unsigned*)(base + 8*40);
        qa[kk][2] = *(const unsigned*)(base + 8);
        qa[kk][3] = *(const unsigned*)(base + 8*40 + 8);
    }

    float oc[4][4];
    #pragma unroll
    for (int v = 0; v < 4; v++)
        #pragma unroll
        for (int e = 0; e < 4; e++) oc[v][e] = 0.f;
    float rs0 = 0.f, rs1 = 0.f;

    int qi0 = q0 + mi*16 + r;
    int qw_min = q0 + mi*16;
    int qw_max = q0 + mi*16 + 15;
    const float sc2 = 0.17677669529663689f * 1.4426950408889634f;
    int nIter = causal ? ((qt + 2) >> 1) : (Lk >> 7);
    int kwbase = kh*64;

    int lrow = (lane & 7) + ((lane >> 4) << 3);
    int lcol = ((lane >> 3) & 1) * 8;
    int vrow = lane & 15;
    int vcol = (lane >> 4) * 8;

    for (int it = 0; it < nIter; it++) {
        int buf = it & 1;
        int k0  = it*128;
        cpa_wait<0>();
        __syncthreads();
        if (it + 1 < nIter) stage_kv(it+1, buf ^ 1);

        int kw0 = k0 + kwbase;
        if (causal && kw0 > qw_max) continue;

        const __half* Ks = KsB[buf];
        const __half* Vs = VsB[buf];
        bool anym = (flags[b*8 + it] != 0);
        bool full = !anym && (!causal || (kw0 + 63 <= qw_min));

        #pragma unroll
        for (int tq = 0; tq < 4; tq++) {
            int kb = kwbase + tq*16;
            unsigned kf0[4], kf1[4];
            ldsm4(kf0, (unsigned)__cvta_generic_to_shared(&Ks[(kb + lrow)*40 + lcol]));
            ldsm4(kf1, (unsigned)__cvta_generic_to_shared(&Ks[(kb + lrow)*40 + 16 + lcol]));

            unsigned pa[4];
            if (full) {
                #pragma unroll
                for (int jj = 0; jj < 2; jj++) {
                    float cf[4] = {0.f, 0.f, 0.f, 0.f};
                    mma16816(cf, qa[0], &kf0[jj*2]);
                    mma16816(cf, qa[1], &kf1[jj*2]);
                    float e0 = ex2(cf[0]*sc2);
                    float e1 = ex2(cf[1]*sc2);
                    float e2 = ex2(cf[2]*sc2);
                    float e3 = ex2(cf[3]*sc2);
                    rs0 += e0 + e1;
                    rs1 += e2 + e3;
                    __half2 plo = __floats2half2_rn(e0, e1);
                    __half2 phi = __floats2half2_rn(e2, e3);
                    pa[jj*2 + 0] = reinterpret_cast<unsigned&>(plo);
                    pa[jj*2 + 1] = reinterpret_cast<unsigned&>(phi);
                }
            } else {
                #pragma unroll
                for (int jj = 0; jj < 2; jj++) {
                    float cf[4] = {0.f, 0.f, 0.f, 0.f};
                    mma16816(cf, qa[0], &kf0[jj*2]);
                    mma16816(cf, qa[1], &kf1[jj*2]);
                    int jcol = kb + jj*8 + g*2;
                    int2 mm = *(const int2*)&smask[buf*128 + jcol];
                    int kgc = k0 + jcol;
                    float e0, e1, e2, e3;
                    if (causal) {
                        e0 = (kgc   <= qi0   && mm.x == 0) ? ex2(cf[0]*sc2) : 0.f;
                        e1 = (kgc+1 <= qi0   && mm.y == 0) ? ex2(cf[1]*sc2) : 0.f;
                        e2 = (kgc   <= qi0+8 && mm.x == 0) ? ex2(cf[2]*sc2) : 0.f;
                        e3 = (kgc+1 <= qi0+8 && mm.y == 0) ? ex2(cf[3]*sc2) : 0.f;
                    } else {
                        e0 = (mm.x == 0) ? ex2(cf[0]*sc2) : 0.f;
                        e1 = (mm.y == 0) ? ex2(cf[1]*sc2) : 0.f;
                        e2 = (mm.x == 0) ? ex2(cf[2]*sc2) : 0.f;
                        e3 = (mm.y == 0) ? ex2(cf[3]*sc2) : 0.f;
                    }
                    rs0 += e0 + e1;
                    rs1 += e2 + e3;
                    __half2 plo = __floats2half2_rn(e0, e1);
                    __half2 phi = __floats2half2_rn(e2, e3);
                    pa[jj*2 + 0] = reinterpret_cast<unsigned&>(plo);
                    pa[jj*2 + 1] = reinterpret_cast<unsigned&>(phi);
                }
            }
            unsigned vb[8];
            ldsm4t(vb,     (unsigned)__cvta_generic_to_shared(&Vs[(kb + vrow)*40 + vcol]));
            ldsm4t(vb + 4, (unsigned)__cvta_generic_to_shared(&Vs[(kb + vrow)*40 + 16 + vcol]));
            #pragma unroll
            for (int v = 0; v < 4; v++)
                mma16816(oc[v], pa, &vb[v*2]);
        }
    }

    rs0 += __shfl_xor_sync(0xffffffffu, rs0, 1);
    rs0 += __shfl_xor_sync(0xffffffffu, rs0, 2);
    rs1 += __shfl_xor_sync(0xffffffffu, rs1, 1);
    rs1 += __shfl_xor_sync(0xffffffffu, rs1, 2);

    __syncthreads();
    float* Ored = (float*)smc;
    float* rsS  = (float*)(smc + 8192);
    if (kh == 1) {
        #pragma unroll
        for (int v = 0; v < 4; v++) {
            int cc = v*8 + g*2;
            Ored[(mi*16 + r)*32 + cc]       = oc[v][0];
            Ored[(mi*16 + r)*32 + cc + 1]   = oc[v][1];
            Ored[(mi*16 + r + 8)*32 + cc]   = oc[v][2];
            Ored[(mi*16 + r + 8)*32 + cc+1] = oc[v][3];
        }
        if (g == 0) { rsS[mi*16 + r] = rs0; rsS[mi*16 + r + 8] = rs1; }
    }
    __syncthreads();
    if (kh == 0) {
        float rt0 = 1.f / (rs0 + rsS[mi*16 + r]);
        float rt1 = 1.f / (rs1 + rsS[mi*16 + r + 8]);
        __half* o0 = Og + ((size_t)(b*SEQ + q0 + mi*16 + r))*DMODEL + h*DHEAD;
        __half* o1 = o0 + (size_t)8*DMODEL;
        #pragma unroll
        for (int v = 0; v < 4; v++) {
            int cc = v*8 + g*2;
            float p00 = (oc[v][0] + Ored[(mi*16 + r)*32 + cc])     * rt0;
            float p01 = (oc[v][1] + Ored[(mi*16 + r)*32 + cc + 1]) * rt0;
            float p10 = (oc[v][2] + Ored[(mi*16 + r + 8)*32 + cc])     * rt1;
            float p11 = (oc[v][3] + Ored[(mi*16 + r + 8)*32 + cc + 1]) * rt1;
            *(__half2*)(o0 + cc) = __floats2half2_rn(p00, p01);
            *(__half2*)(o1 + cc) = __floats2half2_rn(p10, p11);
        }
    }
}

// ---------------- orchestration ----------------
extern "C" void kernel_launch(void* const* d_in, const int* in_sizes, int n_in,
                              void* d_out, int out_size) {
    const float* enc      = (const float*)d_in[0];
    const float* dec      = (const float*)d_in[1];
    const int*   enc_mask = (const int*)  d_in[2];
    const int*   dec_mask = (const int*)  d_in[3];
    const float* W_tgt    = (const float*)d_in[4];
    const float* b_tgt    = (const float*)d_in[5];
    const float* sa_Wq = (const float*)d_in[6];  const float* sa_bq = (const float*)d_in[7];
    const float* sa_Wk = (const float*)d_in[8];  const float* sa_bk = (const float*)d_in[9];
    const float* sa_Wv = (const float*)d_in[10]; const float* sa_bv = (const float*)d_in[11];
    const float* sa_Wo = (const float*)d_in[12]; const float* sa_bo = (const float*)d_in[13];
    const float* sa_g  = (const float*)d_in[14]; const float* sa_b  = (const float*)d_in[15];
    const float* ca_Wq = (const float*)d_in[16]; const float* ca_bq = (const float*)d_in[17];
    const float* ca_Wk = (const float*)d_in[18]; const float* ca_bk = (const float*)d_in[19];
    const float* ca_Wv = (const float*)d_in[20]; const float* ca_bv = (const float*)d_in[21];
    const float* ca_Wo = (const float*)d_in[22]; const float* ca_bo = (const float*)d_in[23];
    const float* ca_g  = (const float*)d_in[24]; const float* ca_b  = (const float*)d_in[25];
    const float* ff_W1 = (const float*)d_in[26]; const float* ff_b1 = (const float*)d_in[27];
    const float* ff_W2 = (const float*)d_in[28]; const float* ff_b2 = (const float*)d_in[29];
    const float* ff_g  = (const float*)d_in[30]; const float* ff_b  = (const float*)d_in[31];

    float* fs = nullptr;
    __half* hs = nullptr;
    int* mflags = nullptr;
    cudaGetSymbolAddress((void**)&fs, g_fscratch);
    cudaGetSymbolAddress((void**)&hs, g_hscratch);
    cudaGetSymbolAddress((void**)&mflags, g_maskflags);
    float* X = fs + OFF_X;
    float* T = fs + OFF_T;
    __half* Xh  = hs + HOFF_XH;
    __half* ENCh= hs + HOFF_ENC;
    __half* Qh  = hs + HOFF_Q;
    __half* Kh  = hs + HOFF_K;
    __half* Vh  = hs + HOFF_V;
    __half* Ch  = hs + HOFF_C;
    __half* Hh  = hs + HOFF_H;
    __half* Wh  = hs + HOFF_W;
    __half* Kc  = hs + HOFF_KC;
    __half* Vc  = hs + HOFF_VC;

    __half* hsaWq = Wh + 0*WSEG;
    __half* hsaWk = Wh + 1*WSEG;
    __half* hsaWv = Wh + 2*WSEG;
    __half* hsaWo = Wh + 3*WSEG;
    __half* hcaWq = Wh + 4*WSEG;
    __half* hcaWk = Wh + 5*WSEG;
    __half* hcaWv = Wh + 6*WSEG;
    __half* hcaWo = Wh + 7*WSEG;
    __half* hffW1 = Wh + 8*WSEG;
    __half* hffW2 = hffW1 + NLAYER*DMODEL*DFF;

    cudaFuncSetAttribute(attn_kernel, cudaFuncAttributeMaxDynamicSharedMemorySize, ATTN_SMEM);
    cudaFuncSetAttribute(gemm_kernel<false,false,true >, cudaFuncAttributeMaxDynamicSharedMemorySize, GEMM_SMEM);
    cudaFuncSetAttribute(gemm_kernel<false,true ,false>, cudaFuncAttributeMaxDynamicSharedMemorySize, GEMM_SMEM);
    cudaFuncSetAttribute(gemm_kernel<true ,false,true >, cudaFuncAttributeMaxDynamicSharedMemorySize, GEMM_SMEM);

    // ---- preamble: mask flags + batched conversion ----
    maskflag_kernel<<<64, 128>>>(dec_mask, enc_mask);
    {
        CvtAll ca;
        const float* srcs[11] = {sa_Wq, sa_Wk, sa_Wv, sa_Wo, ca_Wq, ca_Wk, ca_Wv, ca_Wo,
                                 ff_W1, ff_W2, enc};
        __half* dsts[11] = {hsaWq, hsaWk, hsaWv, hsaWo, hcaWq, hcaWk, hcaWv, hcaWo,
                            hffW1, hffW2, ENCh};
        int nF = NLAYER*DMODEL*DFF;
        int szs[11] = {WSEG,WSEG,WSEG,WSEG,WSEG,WSEG,WSEG,WSEG, nF, nF, TD};
        long total = 0;
        for (int i = 0; i < 11; i++) { ca.src[i]=srcs[i]; ca.dst[i]=dsts[i]; ca.size[i]=szs[i]; total += szs[i]; }
        int nThreads = (int)(total/4);
        cvt_all_kernel<<<(nThreads + 255)/256, 256>>>(ca);
    }

    dim3 blkG(256), blkA(256), blkR(256);
    dim3 g_rows(TOK);
    dim3 g_ln(TOK/8);
    dim3 g_qkv(6, 64);                 // self QKV: 3 sel x 2 ntiles
    dim3 g_q(2, 64);                   // cross Q only
    dim3 g_256(2, 64);
    dim3 g_1024(8, 64);
    dim3 g_ckv(4, 64, NLAYER);         // cross K/V all layers: 2 sel x 2 ntiles x 6
    dim3 g_attn(SEQ/64, NHEAD, BATCH);

    const int WD  = DMODEL*DMODEL;
    const int W1S = DMODEL*DFF;
    const int W2S = DFF*DMODEL;

    // ---- hoisted: all layers' cross-attention K/V from enc (one launch) ----
    {
        GArgs ga{};
        ga.A[0]=ENCh; ga.A[1]=ENCh;
        ga.W[0]=hcaWk; ga.W[1]=hcaWv;
        ga.bi[0]=ca_bk; ga.bi[1]=ca_bv;
        ga.O[0]=Kc; ga.O[1]=Vc;
        gemm_kernel<false,false,true><<<g_ckv, blkG, GEMM_SMEM>>>(ga, nullptr,
            DMODEL, DMODEL, 1, WD, DMODEL, TD);
    }

    embed_kernel<<<g_rows, blkR>>>(dec, W_tgt, b_tgt, X, Xh);

    for (int i = 0; i < NLAYER; i++) {
        // ---- self attention ----
        {
            GArgs ga;
            ga.A[0]=Xh; ga.A[1]=Xh; ga.A[2]=Xh;
            ga.W[0]=hsaWq+i*WD; ga.W[1]=hsaWk+i*WD; ga.W[2]=hsaWv+i*WD;
            ga.bi[0]=sa_bq+i*DMODEL; ga.bi[1]=sa_bk+i*DMODEL; ga.bi[2]=sa_bv+i*DMODEL;
            ga.O[0]=Qh; ga.O[1]=Kh; ga.O[2]=Vh;
            gemm_kernel<false,false,true><<<g_qkv, blkG, GEMM_SMEM>>>(ga, nullptr,
                DMODEL, DMODEL, 1, 0, 0, 0);
        }
        attn_kernel<<<g_attn, blkA, ATTN_SMEM>>>(Qh, Kh, Vh, Ch, dec_mask, mflags, SEQ, 1);
        {
            GArgs ga{};
            ga.A[0]=Ch; ga.W[0]=hsaWo+i*WD; ga.bi[0]=sa_bo+i*DMODEL; ga.O[0]=T;
            gemm_kernel<false,true,false><<<g_256, blkG, GEMM_SMEM>>>(ga, X,
                DMODEL, DMODEL, 1, 0, 0, 0);
        }
        ln_kernel<<<g_ln, blkR>>>(T, sa_g+i*DMODEL, sa_b+i*DMODEL, X, Xh, 0);

        // ---- cross attention (K/V precomputed) ----
        {
            GArgs ga{};
            ga.A[0]=Xh;
            ga.W[0]=hcaWq+i*WD;
            ga.bi[0]=ca_bq+i*DMODEL;
            ga.O[0]=Qh;
            gemm_kernel<false,false,true><<<g_q, blkG, GEMM_SMEM>>>(ga, nullptr,
                DMODEL, DMODEL, 1, 0, 0, 0);
        }
        attn_kernel<<<g_attn, blkA, ATTN_SMEM>>>(Qh, Kc + (size_t)i*TD, Vc + (size_t)i*TD,
                                                 Ch, enc_mask, mflags + 32, SEQ, 0);
        {
            GArgs ga{};
            ga.A[0]=Ch; ga.W[0]=hcaWo+i*WD; ga.bi[0]=ca_bo+i*DMODEL; ga.O[0]=T;
            gemm_kernel<false,true,false><<<g_256, blkG, GEMM_SMEM>>>(ga, X,
                DMODEL, DMODEL, 1, 0, 0, 0);
        }
        ln_kernel<<<g_ln, blkR>>>(T, ca_g+i*DMODEL, ca_b+i*DMODEL, X, Xh, 0);

        // ---- FFN ----
        {
            GArgs ga{};
            ga.A[0]=Xh; ga.W[0]=hffW1+i*W1S; ga.bi[0]=ff_b1+i*DFF; ga.O[0]=Hh;
            gemm_kernel<true,false,true><<<g_1024, blkG, GEMM_SMEM>>>(ga, nullptr,
                DMODEL, DFF, 3, 0, 0, 0);
        }
        {
            GArgs ga{};
            ga.A[0]=Hh; ga.W[0]=hffW2+i*W2S; ga.bi[0]=ff_b2+i*DMODEL; ga.O[0]=T;
            gemm_kernel<false,true,false><<<g_256, blkG, GEMM_SMEM>>>(ga, X,
                DFF, DMODEL, 1, 0, 0, 0);
        }
        ln_kernel<<<g_ln, blkR>>>(T, ff_g+i*DMODEL, ff_b+i*DMODEL, X, Xh,
                                  (i < NLAYER-1) ? 1 : 0);
    }

    cudaMemcpyAsync(d_out, X, (size_t)TD*sizeof(float),
                    cudaMemcpyDeviceToDevice);
}

// round 16
// speedup vs baseline: 1.3246x; 1.3246x over previous
#include <cuda_runtime.h>
#include <cuda_fp16.h>
#include <mma.h>
#include <math.h>

using namespace nvcuda;

#define BATCH   4
#define SEQ     1024
#define DMODEL  256
#define NHEAD   8
#define DHEAD   32
#define DFF     1024
#define NLAYER  6
#define TOK     (BATCH*SEQ)
#define TD      (TOK*DMODEL)          // 1,048,576

__device__ __align__(16) float  g_fscratch[2*TD];
__device__ __align__(16) __half g_hscratch[16*1024*1024];
__device__ __align__(16) float  g_pe[SEQ*DMODEL];
__device__ float g_invf[128];
__device__ int g_maskflags[64];

#define OFF_X 0
#define OFF_T TD

#define HOFF_XH  0
#define HOFF_ENC (1*TD)
#define HOFF_Q   (2*TD)
#define HOFF_K   (3*TD)
#define HOFF_V   (4*TD)
#define HOFF_C   (5*TD)
#define HOFF_H   (6*TD)
#define HOFF_W   (10*TD)
#define WSEG     393216               // NL*256*256

// ---------------- cp.async helpers ----------------
__device__ __forceinline__ void cpa16(void* dst, const void* src) {
    unsigned s = (unsigned)__cvta_generic_to_shared(dst);
    asm volatile("cp.async.cg.shared.global [%0], [%1], 16;\n" :: "r"(s), "l"(src));
}
__device__ __forceinline__ void cpa_commit() {
    asm volatile("cp.async.commit_group;\n");
}
template<int N>
__device__ __forceinline__ void cpa_wait() {
    asm volatile("cp.async.wait_group %0;\n" :: "n"(N));
}

// ---------------- raw mma helpers ----------------
__device__ __forceinline__ void mma16816(float* c, const unsigned* a, const unsigned* b) {
    asm volatile("mma.sync.aligned.m16n8k16.row.col.f32.f16.f16.f32 "
        "{%0,%1,%2,%3}, {%4,%5,%6,%7}, {%8,%9}, {%0,%1,%2,%3};"
        : "+f"(c[0]), "+f"(c[1]), "+f"(c[2]), "+f"(c[3])
        : "r"(a[0]), "r"(a[1]), "r"(a[2]), "r"(a[3]), "r"(b[0]), "r"(b[1]));
}
__device__ __forceinline__ void ldsm4(unsigned* r, unsigned addr) {
    asm volatile("ldmatrix.sync.aligned.m8n8.x4.shared.b16 {%0,%1,%2,%3}, [%4];"
        : "=r"(r[0]), "=r"(r[1]), "=r"(r[2]), "=r"(r[3]) : "r"(addr));
}
__device__ __forceinline__ void ldsm4t(unsigned* r, unsigned addr) {
    asm volatile("ldmatrix.sync.aligned.m8n8.x4.trans.shared.b16 {%0,%1,%2,%3}, [%4];"
        : "=r"(r[0]), "=r"(r[1]), "=r"(r[2]), "=r"(r[3]) : "r"(addr));
}
__device__ __forceinline__ float ex2(float x) {
    float y; asm("ex2.approx.f32 %0, %1;" : "=f"(y) : "f"(x)); return y;
}

// ---------------- mask tile flags ----------------
__global__ void maskflag_kernel(const int* __restrict__ dec_mask,
                                const int* __restrict__ enc_mask) {
    int id = blockIdx.x;
    const int* m = (id < 32) ? dec_mask : enc_mask;
    int loc = id & 31;
    int b = loc >> 3, t = loc & 7;
    int v = m[b*SEQ + t*128 + threadIdx.x];
    int any = __syncthreads_or(v != 0);
    if (threadIdx.x == 0) g_maskflags[id] = any;
}

// ---------------- PE table: invf (double, identical math) then fill ----------
__global__ void invf_kernel() {
    int j = threadIdx.x;   // 0..127
    double e = -(2.0*(double)j/256.0) * 9.210340371976184;  // ln(10000)
    g_invf[j] = (float)exp(e);
}
__global__ void pefill_kernel() {
    int l = blockIdx.x;
    int d = threadIdx.x;
    float arg = (float)l * g_invf[d & 127];
    g_pe[l*DMODEL + d] = (d < 128) ? sinf(arg) : cosf(arg);
}

// ---------------- batched fp32 -> fp16 convert (one launch) ----------------
struct CvtAll {
    const float* src[11];
    __half*      dst[11];
    int          size[11];
};
__global__ void cvt_all_kernel(CvtAll ca) {
    long idx = ((long)blockIdx.x*blockDim.x + threadIdx.x)*4;
    #pragma unroll
    for (int s = 0; s < 11; s++) {
        if (idx < ca.size[s]) {
            float4 v = *(const float4*)&ca.src[s][idx];
            __half2* o = (__half2*)&ca.dst[s][idx];
            o[0] = __floats2half2_rn(v.x, v.y);
            o[1] = __floats2half2_rn(v.z, v.w);
            return;
        }
        idx -= ca.size[s];
    }
}

// ---------------- embed (+PE layer 0, table read) ----------------
__global__ void embed_kernel(const float* __restrict__ dec,
                             const float* __restrict__ W,
                             const float* __restrict__ b,
                             float* __restrict__ x, __half* __restrict__ xh) {
    int row = blockIdx.x;
    int d   = threadIdx.x;
    const float* in = dec + row*3;
    float acc = b[d] + in[0]*W[d] + in[1]*W[DMODEL+d] + in[2]*W[2*DMODEL+d]
              + g_pe[(row & (SEQ-1))*DMODEL + d];
    x [row*DMODEL + d] = acc;
    xh[row*DMODEL + d] = __float2half(acc);
}

// ---------------- LayerNorm: warp-per-row, PE from table ----------------
__global__ __launch_bounds__(256)
void ln_kernel(const float* __restrict__ t,
               const float* __restrict__ g,
               const float* __restrict__ b,
               float* __restrict__ out, __half* __restrict__ outh,
               int addpe) {
    int w    = threadIdx.x >> 5;
    int lane = threadIdx.x & 31;
    int row  = blockIdx.x*8 + w;
    int cb   = lane*8;

    const float* tr = t + (size_t)row*DMODEL + cb;
    float4 v0 = *(const float4*)tr;
    float4 v1 = *(const float4*)(tr + 4);

    float s1 = (v0.x + v0.y) + (v0.z + v0.w) + (v1.x + v1.y) + (v1.z + v1.w);
    float s2 = v0.x*v0.x + v0.y*v0.y + v0.z*v0.z + v0.w*v0.w
             + v1.x*v1.x + v1.y*v1.y + v1.z*v1.z + v1.w*v1.w;
    #pragma unroll
    for (int o = 16; o; o >>= 1) {
        s1 += __shfl_xor_sync(0xffffffffu, s1, o);
        s2 += __shfl_xor_sync(0xffffffffu, s2, o);
    }
    float mean = s1 * (1.0f/DMODEL);
    float var  = s2 * (1.0f/DMODEL) - mean*mean;
    float rstd = rsqrtf(var + 1e-5f);

    float4 g0 = *(const float4*)&g[cb];
    float4 g1 = *(const float4*)&g[cb + 4];
    float4 e0 = *(const float4*)&b[cb];
    float4 e1 = *(const float4*)&b[cb + 4];

    float o8[8];
    o8[0]=(v0.x-mean)*rstd*g0.x+e0.x; o8[1]=(v0.y-mean)*rstd*g0.y+e0.y;
    o8[2]=(v0.z-mean)*rstd*g0.z+e0.z; o8[3]=(v0.w-mean)*rstd*g0.w+e0.w;
    o8[4]=(v1.x-mean)*rstd*g1.x+e1.x; o8[5]=(v1.y-mean)*rstd*g1.y+e1.y;
    o8[6]=(v1.z-mean)*rstd*g1.z+e1.z; o8[7]=(v1.w-mean)*rstd*g1.w+e1.w;
    if (addpe) {
        const float* pp = &g_pe[(row & (SEQ-1))*DMODEL + cb];
        float4 p0 = *(const float4*)pp;
        float4 p1 = *(const float4*)(pp + 4);
        o8[0]+=p0.x; o8[1]+=p0.y; o8[2]+=p0.z; o8[3]+=p0.w;
        o8[4]+=p1.x; o8[5]+=p1.y; o8[6]+=p1.z; o8[7]+=p1.w;
    }
    float* op = out + (size_t)row*DMODEL + cb;
    *(float4*)op       = make_float4(o8[0],o8[1],o8[2],o8[3]);
    *(float4*)(op + 4) = make_float4(o8[4],o8[5],o8[6],o8[7]);
    __half2* hp = (__half2*)(outh + (size_t)row*DMODEL + cb);
    hp[0] = __floats2half2_rn(o8[0], o8[1]);
    hp[1] = __floats2half2_rn(o8[2], o8[3]);
    hp[2] = __floats2half2_rn(o8[4], o8[5]);
    hp[3] = __floats2half2_rn(o8[6], o8[7]);
}

// ---------------- fp16 wmma GEMM (round-13 config): 64x128x64, 3-stage ------
struct GArgs {
    const __half* A[3];
    const __half* W[3];
    const float*  bi[3];
    void*         O[3];
};

#define AS_H 72
#define BS_H 136
#define GEMM_SMEM ((3*64*AS_H + 3*64*BS_H)*2)   // 79872 B

template<bool RELU, bool RES, bool OUTH>
__global__ __launch_bounds__(256)
void gemm_kernel(GArgs ga, const float* __restrict__ Rres,
                 int K, int N, int bnshift) {
    extern __shared__ __align__(16) char dsmc[];
    __half* As = (__half*)dsmc;
    __half* Bs = As + 3*64*AS_H;

    int tid = threadIdx.x;
    int w   = tid >> 5;
    int bx  = blockIdx.x;
    int sel = bx >> bnshift;
    int bn  = bx & ((1 << bnshift) - 1);
    int bm  = blockIdx.y;

    const __half* Abase = ga.A[sel] + (size_t)(bm*64)*K;
    const __half* Wbase = ga.W[sel] + bn*128;
    const float*  bias  = ga.bi[sel];

    int wm = w & 1;
    int wn = w >> 1;

    wmma::fragment<wmma::accumulator,16,16,16,float> c[2][2];
    #pragma unroll
    for (int i = 0; i < 2; i++)
        #pragma unroll
        for (int j = 0; j < 2; j++)
            wmma::fill_fragment(c[i][j], 0.0f);

    auto stage = [&](int t, int buf) {
        __half* Ab = As + buf*64*AS_H;
        __half* Bb = Bs + buf*64*BS_H;
        const __half* Ag = Abase + t*64;
        #pragma unroll
        for (int i = 0; i < 2; i++) {
            int s = tid + i*256;
            int r = s >> 3, c8 = s & 7;
            cpa16(&Ab[r*AS_H + c8*8], Ag + (size_t)r*K + c8*8);
        }
        const __half* Wg = Wbase + (size_t)(t*64)*N;
        #pragma unroll
        for (int i = 0; i < 4; i++) {
            int s = tid + i*256;
            int r = s >> 4, c8 = s & 15;
            cpa16(&Bb[r*BS_H + c8*8], Wg + (size_t)r*N + c8*8);
        }
        cpa_commit();
    };

    int T = K >> 6;
    stage(0, 0);
    if (T > 1) stage(1, 1);

    for (int t = 0; t < T; t++) {
        if (t + 1 < T) cpa_wait<1>(); else cpa_wait<0>();
        __syncthreads();
        if (t + 2 < T) stage(t+2, (t+2)%3);

        int buf = t % 3;
        __half* Ab = As + buf*64*AS_H;
        __half* Bb = Bs + buf*64*BS_H;
        #pragma unroll
        for (int kk = 0; kk < 4; kk++) {
            wmma::fragment<wmma::matrix_a,16,16,16,__half,wmma::row_major> a[2];
            #pragma unroll
            for (int i = 0; i < 2; i++)
                wmma::load_matrix_sync(a[i], &Ab[(wm*32 + i*16)*AS_H + kk*16], AS_H);
            #pragma unroll
            for (int j = 0; j < 2; j++) {
                wmma::fragment<wmma::matrix_b,16,16,16,__half,wmma::row_major> bf;
                wmma::load_matrix_sync(bf, &Bb[(kk*16)*BS_H + wn*32 + j*16], BS_H);
                #pragma unroll
                for (int i = 0; i < 2; i++)
                    wmma::mma_sync(c[i][j], a[i], bf, c[i][j]);
            }
        }
    }
    __syncthreads();

    float* Cs = (float*)dsmc;
    #pragma unroll
    for (int i = 0; i < 2; i++)
        #pragma unroll
        for (int j = 0; j < 2; j++)
            wmma::store_matrix_sync(&Cs[(wm*32 + i*16)*136 + wn*32 + j*16],
                                    c[i][j], 136, wmma::mem_row_major);
    __syncthreads();

    #pragma unroll
    for (int i = 0; i < 8; i++) {
        int s = tid + i*256;
        int r = s >> 5, c4 = s & 31;
        int gr = bm*64 + r;
        int gc = bn*128 + c4*4;
        float4 v  = *(float4*)&Cs[r*136 + c4*4];
        float4 bb = *(const float4*)&bias[gc];
        v.x += bb.x; v.y += bb.y; v.z += bb.z; v.w += bb.w;
        if (RES) {
            float4 rr = *(const float4*)&Rres[(size_t)gr*N + gc];
            v.x += rr.x; v.y += rr.y; v.z += rr.z; v.w += rr.w;
        }
        if (RELU) {
            v.x = fmaxf(v.x, 0.f); v.y = fmaxf(v.y, 0.f);
            v.z = fmaxf(v.z, 0.f); v.w = fmaxf(v.w, 0.f);
        }
        if (OUTH) {
            __half2* op = (__half2*)((__half*)ga.O[sel] + (size_t)gr*N + gc);
            op[0] = __floats2half2_rn(v.x, v.y);
            op[1] = __floats2half2_rn(v.z, v.w);
        } else {
            *(float4*)((float*)ga.O[sel] + (size_t)gr*N + gc) = v;
        }
    }
}

// ---------------- fused attention v5 (unchanged, passing) ----------------
#define ATTN_SMEM 47104

__global__ __launch_bounds__(256)
void attn_kernel(const __half* __restrict__ Qg, const __half* __restrict__ Kg,
                 const __half* __restrict__ Vg, __half* __restrict__ Og,
                 const int* __restrict__ mask, const int* __restrict__ flags,
                 int Lk, int causal) {
    extern __shared__ __align__(16) char smc[];
    __half* Qs     = (__half*)smc;
    __half* KsB[2] = {(__half*)(smc + 5120),  (__half*)(smc + 15360)};
    __half* VsB[2] = {(__half*)(smc + 25600), (__half*)(smc + 35840)};
    int*    smask  = (int*)(smc + 46080);

    int tid = threadIdx.x, w = tid >> 5, lane = tid & 31;
    int qt = blockIdx.x, h = blockIdx.y, b = blockIdx.z;
    int q0 = qt*64;
    int mi = w & 3, kh = w >> 2;
    int r  = lane >> 2, g = lane & 3;

    const __half* Qp = Qg + ((size_t)(b*SEQ + q0))*DMODEL + h*DHEAD;
    {
        int rr = tid >> 2, c8 = tid & 3;
        *(float4*)&Qs[rr*40 + c8*8] = *(const float4*)&Qp[(size_t)rr*DMODEL + c8*8];
    }

    auto stage_kv = [&](int it, int buf) {
        int k0 = it*128;
        const __half* Kp = Kg + ((size_t)(b*Lk + k0))*DMODEL + h*DHEAD;
        const __half* Vp = Vg + ((size_t)(b*Lk + k0))*DMODEL + h*DHEAD;
        #pragma unroll
        for (int i = 0; i < 2; i++) {
            int s = tid + i*256;
            int rr = s >> 2, c8 = s & 3;
            cpa16(&KsB[buf][rr*40 + c8*8], Kp + (size_t)rr*DMODEL + c8*8);
            cpa16(&VsB[buf][rr*40 + c8*8], Vp + (size_t)rr*DMODEL + c8*8);
        }
        if (tid < 128) smask[buf*128 + tid] = mask[b*Lk + k0 + tid];
        cpa_commit();
    };

    stage_kv(0, 0);
    __syncthreads();

    unsigned qa[2][4];
    #pragma unroll
    for (int kk = 0; kk < 2; kk++) {
        const __half* base = &Qs[(mi*16 + r)*40 + kk*16 + g*2];
        qa[kk][0] = *(const unsigned*)(base);
        qa[kk][1] = *(const unsigned*)(base + 8*40);
        qa[kk][2] = *(const unsigned*)(base + 8);
        qa[kk][3] = *(const unsigned*)(base + 8*40 + 8);
    }

    float oc[4][4];
    #pragma unroll
    for (int v = 0; v < 4; v++)
        #pragma unroll
        for (int e = 0; e < 4; e++) oc[v][e] = 0.f;
    float rs0 = 0.f, rs1 = 0.f;

    int qi0 = q0 + mi*16 + r;
    int qw_min = q0 + mi*16;
    int qw_max = q0 + mi*16 + 15;
    const float sc2 = 0.17677669529663689f * 1.4426950408889634f;
    int nIter = causal ? ((qt + 2) >> 1) : (Lk >> 7);
    int kwbase = kh*64;

    int lrow = (lane & 7) + ((lane >> 4) << 3);
    int lcol = ((lane >> 3) & 1) * 8;
    int vrow = lane & 15;
    int vcol = (lane >> 4) * 8;

    for (int it = 0; it < nIter; it++) {
        int buf = it & 1;
        int k0  = it*128;
        cpa_wait<0>();
        __syncthreads();
        if (it + 1 < nIter) stage_kv(it+1, buf ^ 1);

        int kw0 = k0 + kwbase;
        if (causal && kw0 > qw_max) continue;

        const __half* Ks = KsB[buf];
        const __half* Vs = VsB[buf];
        bool anym = (flags[b*8 + it] != 0);
        bool full = !anym && (!causal || (kw0 + 63 <= qw_min));

        #pragma unroll
        for (int tq = 0; tq < 4; tq++) {
            int kb = kwbase + tq*16;
            unsigned kf0[4], kf1[4];
            ldsm4(kf0, (unsigned)__cvta_generic_to_shared(&Ks[(kb + lrow)*40 + lcol]));
            ldsm4(kf1, (unsigned)__cvta_generic_to_shared(&Ks[(kb + lrow)*40 + 16 + lcol]));

            unsigned pa[4];
            if (full) {
                #pragma unroll
                for (int jj = 0; jj < 2; jj++) {
                    float cf[4] = {0.f, 0.f, 0.f, 0.f};
                    mma16816(cf, qa[0], &kf0[jj*2]);
                    mma16816(cf, qa[1], &kf1[jj*2]);
                    float e0 = ex2(cf[0]*sc2);
                    float e1 = ex2(cf[1]*sc2);
                    float e2 = ex2(cf[2]*sc2);
                    float e3 = ex2(cf[3]*sc2);
                    rs0 += e0 + e1;
                    rs1 += e2 + e3;
                    __half2 plo = __floats2half2_rn(e0, e1);
                    __half2 phi = __floats2half2_rn(e2, e3);
                    pa[jj*2 + 0] = reinterpret_cast<unsigned&>(plo);
                    pa[jj*2 + 1] = reinterpret_cast<unsigned&>(phi);
                }
            } else {
                #pragma unroll
                for (int jj = 0; jj < 2; jj++) {
                    float cf[4] = {0.f, 0.f, 0.f, 0.f};
                    mma16816(cf, qa[0], &kf0[jj*2]);
                    mma16816(cf, qa[1], &kf1[jj*2]);
                    int jcol = kb + jj*8 + g*2;
                    int2 mm = *(const int2*)&smask[buf*128 + jcol];
                    int kgc = k0 + jcol;
                    float e0, e1, e2, e3;
                    if (causal) {
                        e0 = (kgc   <= qi0   && mm.x == 0) ? ex2(cf[0]*sc2) : 0.f;
                        e1 = (kgc+1 <= qi0   && mm.y == 0) ? ex2(cf[1]*sc2) : 0.f;
                        e2 = (kgc   <= qi0+8 && mm.x == 0) ? ex2(cf[2]*sc2) : 0.f;
                        e3 = (kgc+1 <= qi0+8 && mm.y == 0) ? ex2(cf[3]*sc2) : 0.f;
                    } else {
                        e0 = (mm.x == 0) ? ex2(cf[0]*sc2) : 0.f;
                        e1 = (mm.y == 0) ? ex2(cf[1]*sc2) : 0.f;
                        e2 = (mm.x == 0) ? ex2(cf[2]*sc2) : 0.f;
                        e3 = (mm.y == 0) ? ex2(cf[3]*sc2) : 0.f;
                    }
                    rs0 += e0 + e1;
                    rs1 += e2 + e3;
                    __half2 plo = __floats2half2_rn(e0, e1);
                    __half2 phi = __floats2half2_rn(e2, e3);
                    pa[jj*2 + 0] = reinterpret_cast<unsigned&>(plo);
                    pa[jj*2 + 1] = reinterpret_cast<unsigned&>(phi);
                }
            }
            unsigned vb[8];
            ldsm4t(vb,     (unsigned)__cvta_generic_to_shared(&Vs[(kb + vrow)*40 + vcol]));
            ldsm4t(vb + 4, (unsigned)__cvta_generic_to_shared(&Vs[(kb + vrow)*40 + 16 + vcol]));
            #pragma unroll
            for (int v = 0; v < 4; v++)
                mma16816(oc[v], pa, &vb[v*2]);
        }
    }

    rs0 += __shfl_xor_sync(0xffffffffu, rs0, 1);
    rs0 += __shfl_xor_sync(0xffffffffu, rs0, 2);
    rs1 += __shfl_xor_sync(0xffffffffu, rs1, 1);
    rs1 += __shfl_xor_sync(0xffffffffu, rs1, 2);

    __syncthreads();
    float* Ored = (float*)smc;
    float* rsS  = (float*)(smc + 8192);
    if (kh == 1) {
        #pragma unroll
        for (int v = 0; v < 4; v++) {
            int cc = v*8 + g*2;
            Ored[(mi*16 + r)*32 + cc]       = oc[v][0];
            Ored[(mi*16 + r)*32 + cc + 1]   = oc[v][1];
            Ored[(mi*16 + r + 8)*32 + cc]   = oc[v][2];
            Ored[(mi*16 + r + 8)*32 + cc+1] = oc[v][3];
        }
        if (g == 0) { rsS[mi*16 + r] = rs0; rsS[mi*16 + r + 8] = rs1; }
    }
    __syncthreads();
    if (kh == 0) {
        float rt0 = 1.f / (rs0 + rsS[mi*16 + r]);
        float rt1 = 1.f / (rs1 + rsS[mi*16 + r + 8]);
        __half* o0 = Og + ((size_t)(b*SEQ + q0 + mi*16 + r))*DMODEL + h*DHEAD;
        __half* o1 = o0 + (size_t)8*DMODEL;
        #pragma unroll
        for (int v = 0; v < 4; v++) {
            int cc = v*8 + g*2;
            float p00 = (oc[v][0] + Ored[(mi*16 + r)*32 + cc])     * rt0;
            float p01 = (oc[v][1] + Ored[(mi*16 + r)*32 + cc + 1]) * rt0;
            float p10 = (oc[v][2] + Ored[(mi*16 + r + 8)*32 + cc])     * rt1;
            float p11 = (oc[v][3] + Ored[(mi*16 + r + 8)*32 + cc + 1]) * rt1;
            *(__half2*)(o0 + cc) = __floats2half2_rn(p00, p01);
            *(__half2*)(o1 + cc) = __floats2half2_rn(p10, p11);
        }
    }
}

// ---------------- orchestration ----------------
extern "C" void kernel_launch(void* const* d_in, const int* in_sizes, int n_in,
                              void* d_out, int out_size) {
    const float* enc      = (const float*)d_in[0];
    const float* dec      = (const float*)d_in[1];
    const int*   enc_mask = (const int*)  d_in[2];
    const int*   dec_mask = (const int*)  d_in[3];
    const float* W_tgt    = (const float*)d_in[4];
    const float* b_tgt    = (const float*)d_in[5];
    const float* sa_Wq = (const float*)d_in[6];  const float* sa_bq = (const float*)d_in[7];
    const float* sa_Wk = (const float*)d_in[8];  const float* sa_bk = (const float*)d_in[9];
    const float* sa_Wv = (const float*)d_in[10]; const float* sa_bv = (const float*)d_in[11];
    const float* sa_Wo = (const float*)d_in[12]; const float* sa_bo = (const float*)d_in[13];
    const float* sa_g  = (const float*)d_in[14]; const float* sa_b  = (const float*)d_in[15];
    const float* ca_Wq = (const float*)d_in[16]; const float* ca_bq = (const float*)d_in[17];
    const float* ca_Wk = (const float*)d_in[18]; const float* ca_bk = (const float*)d_in[19];
    const float* ca_Wv = (const float*)d_in[20]; const float* ca_bv = (const float*)d_in[21];
    const float* ca_Wo = (const float*)d_in[22]; const float* ca_bo = (const float*)d_in[23];
    const float* ca_g  = (const float*)d_in[24]; const float* ca_b  = (const float*)d_in[25];
    const float* ff_W1 = (const float*)d_in[26]; const float* ff_b1 = (const float*)d_in[27];
    const float* ff_W2 = (const float*)d_in[28]; const float* ff_b2 = (const float*)d_in[29];
    const float* ff_g  = (const float*)d_in[30]; const float* ff_b  = (const float*)d_in[31];

    float* fs = nullptr;
    __half* hs = nullptr;
    int* mflags = nullptr;
    cudaGetSymbolAddress((void**)&fs, g_fscratch);
    cudaGetSymbolAddress((void**)&hs, g_hscratch);
    cudaGetSymbolAddress((void**)&mflags, g_maskflags);
    float* X = fs + OFF_X;
    float* T = fs + OFF_T;
    __half* Xh  = hs + HOFF_XH;
    __half* ENCh= hs + HOFF_ENC;
    __half* Qh  = hs + HOFF_Q;
    __half* Kh  = hs + HOFF_K;
    __half* Vh  = hs + HOFF_V;
    __half* Ch  = hs + HOFF_C;
    __half* Hh  = hs + HOFF_H;
    __half* Wh  = hs + HOFF_W;

    __half* hsaWq = Wh + 0*WSEG;
    __half* hsaWk = Wh + 1*WSEG;
    __half* hsaWv = Wh + 2*WSEG;
    __half* hsaWo = Wh + 3*WSEG;
    __half* hcaWq = Wh + 4*WSEG;
    __half* hcaWk = Wh + 5*WSEG;
    __half* hcaWv = Wh + 6*WSEG;
    __half* hcaWo = Wh + 7*WSEG;
    __half* hffW1 = Wh + 8*WSEG;
    __half* hffW2 = hffW1 + NLAYER*DMODEL*DFF;

    cudaFuncSetAttribute(attn_kernel, cudaFuncAttributeMaxDynamicSharedMemorySize, ATTN_SMEM);
    cudaFuncSetAttribute(gemm_kernel<false,false,true >, cudaFuncAttributeMaxDynamicSharedMemorySize, GEMM_SMEM);
    cudaFuncSetAttribute(gemm_kernel<false,true ,false>, cudaFuncAttributeMaxDynamicSharedMemorySize, GEMM_SMEM);
    cudaFuncSetAttribute(gemm_kernel<true ,false,true >, cudaFuncAttributeMaxDynamicSharedMemorySize, GEMM_SMEM);

    // ---- preamble: PE table + mask flags + batched conversion ----
    invf_kernel<<<1, 128>>>();
    pefill_kernel<<<SEQ, DMODEL>>>();
    maskflag_kernel<<<64, 128>>>(dec_mask, enc_mask);
    {
        CvtAll ca;
        const float* srcs[11] = {sa_Wq, sa_Wk, sa_Wv, sa_Wo, ca_Wq, ca_Wk, ca_Wv, ca_Wo,
                                 ff_W1, ff_W2, enc};
        __half* dsts[11] = {hsaWq, hsaWk, hsaWv, hsaWo, hcaWq, hcaWk, hcaWv, hcaWo,
                            hffW1, hffW2, ENCh};
        int nF = NLAYER*DMODEL*DFF;
        int szs[11] = {WSEG,WSEG,WSEG,WSEG,WSEG,WSEG,WSEG,WSEG, nF, nF, TD};
        long total = 0;
        for (int i = 0; i < 11; i++) { ca.src[i]=srcs[i]; ca.dst[i]=dsts[i]; ca.size[i]=szs[i]; total += szs[i]; }
        int nThreads = (int)(total/4);
        cvt_all_kernel<<<(nThreads + 255)/256, 256>>>(ca);
    }

    dim3 blkG(256), blkA(256), blkR(256);
    dim3 g_rows(TOK);
    dim3 g_ln(TOK/8);
    dim3 g_qkv(6, 64);
    dim3 g_256(2, 64);
    dim3 g_1024(8, 64);
    dim3 g_attn(SEQ/64, NHEAD, BATCH);

    embed_kernel<<<g_rows, blkR>>>(dec, W_tgt, b_tgt, X, Xh);

    const int WD  = DMODEL*DMODEL;
    const int W1S = DMODEL*DFF;
    const int W2S = DFF*DMODEL;

    for (int i = 0; i < NLAYER; i++) {
        // ---- self attention ----
        {
            GArgs ga;
            ga.A[0]=Xh; ga.A[1]=Xh; ga.A[2]=Xh;
            ga.W[0]=hsaWq+i*WD; ga.W[1]=hsaWk+i*WD; ga.W[2]=hsaWv+i*WD;
            ga.bi[0]=sa_bq+i*DMODEL; ga.bi[1]=sa_bk+i*DMODEL; ga.bi[2]=sa_bv+i*DMODEL;
            ga.O[0]=Qh; ga.O[1]=Kh; ga.O[2]=Vh;
            gemm_kernel<false,false,true><<<g_qkv, blkG, GEMM_SMEM>>>(ga, nullptr, DMODEL, DMODEL, 1);
        }
        attn_kernel<<<g_attn, blkA, ATTN_SMEM>>>(Qh, Kh, Vh, Ch, dec_mask, mflags, SEQ, 1);
        {
            GArgs ga{};
            ga.A[0]=Ch; ga.W[0]=hsaWo+i*WD; ga.bi[0]=sa_bo+i*DMODEL; ga.O[0]=T;
            gemm_kernel<false,true,false><<<g_256, blkG, GEMM_SMEM>>>(ga, X, DMODEL, DMODEL, 1);
        }
        ln_kernel<<<g_ln, blkR>>>(T, sa_g+i*DMODEL, sa_b+i*DMODEL, X, Xh, 0);

        // ---- cross attention ----
        {
            GArgs ga;
            ga.A[0]=Xh; ga.A[1]=ENCh; ga.A[2]=ENCh;
            ga.W[0]=hcaWq+i*WD; ga.W[1]=hcaWk+i*WD; ga.W[2]=hcaWv+i*WD;
            ga.bi[0]=ca_bq+i*DMODEL; ga.bi[1]=ca_bk+i*DMODEL; ga.bi[2]=ca_bv+i*DMODEL;
            ga.O[0]=Qh; ga.O[1]=Kh; ga.O[2]=Vh;
            gemm_kernel<false,false,true><<<g_qkv, blkG, GEMM_SMEM>>>(ga, nullptr, DMODEL, DMODEL, 1);
        }
        attn_kernel<<<g_attn, blkA, ATTN_SMEM>>>(Qh, Kh, Vh, Ch, enc_mask, mflags + 32, SEQ, 0);
        {
            GArgs ga{};
            ga.A[0]=Ch; ga.W[0]=hcaWo+i*WD; ga.bi[0]=ca_bo+i*DMODEL; ga.O[0]=T;
            gemm_kernel<false,true,false><<<g_256, blkG, GEMM_SMEM>>>(ga, X, DMODEL, DMODEL, 1);
        }
        ln_kernel<<<g_ln, blkR>>>(T, ca_g+i*DMODEL, ca_b+i*DMODEL, X, Xh, 0);

        // ---- FFN ----
        {
            GArgs ga{};
            ga.A[0]=Xh; ga.W[0]=hffW1+i*W1S; ga.bi[0]=ff_b1+i*DFF; ga.O[0]=Hh;
            gemm_kernel<true,false,true><<<g_1024, blkG, GEMM_SMEM>>>(ga, nullptr, DMODEL, DFF, 3);
        }
        {
            GArgs ga{};
            ga.A[0]=Hh; ga.W[0]=hffW2+i*W2S; ga.bi[0]=ff_b2+i*DMODEL; ga.O[0]=T;
            gemm_kernel<false,true,false><<<g_256, blkG, GEMM_SMEM>>>(ga, X, DFF, DMODEL, 1);
        }
        ln_kernel<<<g_ln, blkR>>>(T, ff_g+i*DMODEL, ff_b+i*DMODEL, X, Xh, (i < NLAYER-1) ? 1 : 0);
    }

    cudaMemcpyAsync(d_out, X, (size_t)TD*sizeof(float),
                    cudaMemcpyDeviceToDevice);
}